// round 10
// baseline (speedup 1.0000x reference)
#include <cuda_runtime.h>

// Exact L-inf nearest neighbor, scan-free bucket grid. 4 kernels:
//   zero_k   : zero per-cell counts (halo grid) + counters. Fully parallel.
//   bucket_k : per point: atomicAdd rank; rank<K -> bucket slot, else global
//              overflow list (exactness preserved: EVERY query scans the
//              whole overflow list, and extra real candidates are harmless).
//   fast_k   : 4 lanes/query; 9 halo cells cell-per-lane (no boundary
//              branches), u64 pack+min, ovf sweep, wall-bound accept;
//              failures stash (q, best) for resume.
//   slow_k   : one warp per failed query; RESUMES at ring 2 with fast's
//              best; expanding Chebyshev rings over buckets + wall bounds.
// u64 pack (d_bits<<32 | idx<<19 | ovf<<18 | pos): min() IS the
// lexicographic (d, idx) compare -> exact jnp.argmin tie semantics.
// Wall soundness: out-of-range B points clamp into edge cells, so a wall
// touching the grid edge is dropped; every unscanned point lies strictly
// beyond a remaining wall (EPS-strict accept).

#define G      128
#define GH     (G + 2)                    // halo
#define NH     (GH * GH)                  // 16900
#define K      8
#define X0     (-4.5f)
#define EXT    9.0f
#define H      (EXT / (float)G)           // 0.0703125, binary exact
#define INVH   ((float)G / EXT)
#define EPS    1e-6f

__device__ int    g_cnt[NH];
__device__ float4 g_bkt[NH * K];          // (x, y, payload_bits, 0)
__device__ int    g_ovf_cnt;
__device__ float4 g_ovf[4096];
__device__ int    g_fail_cnt;
__device__ int    g_fail_q[32768];
__device__ unsigned long long g_fail_best[32768];

__device__ __forceinline__ int cell_coord(float v) {
    int c = __float2int_rd((v - X0) * INVH);
    return min(max(c, 0), G - 1);
}

// ---------------- build ----------------
__global__ void __launch_bounds__(256)
zero_k()
{
    int i = blockIdx.x * 256 + threadIdx.x;
    if (i < NH) g_cnt[i] = 0;
    if (i == 0) { g_ovf_cnt = 0; g_fail_cnt = 0; }
}

__global__ void __launch_bounds__(256)
bucket_k(const float* __restrict__ B, int N)
{
    int n = blockIdx.x * 256 + threadIdx.x;
    if (n >= N) return;
    float x = __ldg(&B[n]), y = __ldg(&B[N + n]);
    int h = (cell_coord(y) + 1) * GH + (cell_coord(x) + 1);
    int rank = atomicAdd(&g_cnt[h], 1);
    if (rank < K) {
        int pos = h * K + rank;
        unsigned pay = ((unsigned)n << 19) | (unsigned)pos;
        g_bkt[pos] = make_float4(x, y, __uint_as_float(pay), 0.0f);
    } else {
        int o = atomicAdd(&g_ovf_cnt, 1);
        unsigned pay = ((unsigned)n << 19) | (1u << 18) | (unsigned)o;
        g_ovf[o] = make_float4(x, y, __uint_as_float(pay), 0.0f);
    }
}

// ---------------- query helpers ----------------
__device__ __forceinline__ void eval_pt(float4 pt, float ax, float ay,
                                        unsigned long long& best)
{
    float d = fmaxf(fabsf(ax - pt.x), fabsf(ay - pt.y));
    unsigned long long c = (((unsigned long long)__float_as_uint(d)) << 32)
                         | (unsigned long long)__float_as_uint(pt.z);
    best = min(best, c);
}

__device__ __forceinline__ void scan_hcell(int h, float ax, float ay,
                                           unsigned long long& best)
{
    int cnt = min(__ldg(&g_cnt[h]), K);
    const float4* bp = &g_bkt[h * K];
    for (int j = 0; j < cnt; ++j) eval_pt(__ldg(&bp[j]), ax, ay, best);
}

__device__ __forceinline__ float2 fetch_win(unsigned long long best,
                                            float ax, float ay)
{
    unsigned pay = (unsigned)best;
    int pos = (int)(pay & 0x3FFFFu);
    float4 pt = (pay & (1u << 18)) ? __ldg(&g_ovf[pos]) : __ldg(&g_bkt[pos]);
    return make_float2(ax - pt.x, ay - pt.y);
}

// ---------------- fast kernel: 4 lanes/query ----------------
__global__ void __launch_bounds__(256, 8)
fast_k(const float* __restrict__ A, float* __restrict__ out, int Q)
{
    const int tid  = blockIdx.x * 256 + threadIdx.x;
    const int q    = tid >> 2;
    const int lane = tid & 3;
    if (q >= Q) return;

    const unsigned gmask = 0xFu << (threadIdx.x & 28);

    const float2 aq = __ldg(&((const float2*)A)[q]);
    const float ax = aq.x, ay = aq.y;
    const int cx = cell_coord(ax);
    const int cy = cell_coord(ay);
    const int hc = (cy + 1) * GH + (cx + 1);     // halo center cell

    unsigned long long best = 0xFFFFFFFFFFFFFFFFull;

    // cells 0..8 of the 3x3: lane l -> l, l+4, (lane0 also 8). Halo => no
    // boundary branches; halo cells have cnt 0.
    {
        int c1 = lane, c2 = lane + 4;
        int h1 = hc + (c1 / 3 - 1) * GH + (c1 % 3 - 1);
        int h2 = hc + (c2 / 3 - 1) * GH + (c2 % 3 - 1);
        scan_hcell(h1, ax, ay, best);
        scan_hcell(h2, ax, ay, best);
        if (lane == 0) scan_hcell(hc + GH + 1, ax, ay, best);  // cell 8
    }
    // full overflow sweep (expected 0..3 entries) - extra real candidates OK
    {
        int oc = g_ovf_cnt;
        for (int o = lane; o < oc; o += 4)
            eval_pt(__ldg(&g_ovf[o]), ax, ay, best);
    }

    best = min(best, __shfl_xor_sync(gmask, best, 2));
    best = min(best, __shfl_xor_sync(gmask, best, 1));

    if (lane == 0) {
        float mb = __int_as_float(0x7f800000);
        if (cx - 1 > 0)     mb = fminf(mb, ax - (X0 + (float)(cx - 1) * H));
        if (cx + 1 < G - 1) mb = fminf(mb, (X0 + (float)(cx + 2) * H) - ax);
        if (cy - 1 > 0)     mb = fminf(mb, ay - (X0 + (float)(cy - 1) * H));
        if (cy + 1 < G - 1) mb = fminf(mb, (X0 + (float)(cy + 2) * H) - ay);

        float bd = __uint_as_float((unsigned)(best >> 32));
        if (bd <= mb - EPS) {
            ((float2*)out)[q] = fetch_win(best, ax, ay);
        } else {
            int slot = atomicAdd(&g_fail_cnt, 1);
            g_fail_q[slot]    = q;
            g_fail_best[slot] = best;
        }
    }
}

// ---------------- slow kernel: one warp per failed query, resume r=2 -----
__global__ void __launch_bounds__(256)
slow_k(const float* __restrict__ A, float* __restrict__ out, int nwarps_total)
{
    const int wglob = blockIdx.x * 8 + (threadIdx.x >> 5);
    const int lane  = threadIdx.x & 31;
    const int cnt   = g_fail_cnt;

    for (int f = wglob; f < cnt; f += nwarps_total) {
        const int q = g_fail_q[f];
        const float2 aq = __ldg(&((const float2*)A)[q]);
        const float ax = aq.x, ay = aq.y;
        const int cx = cell_coord(ax);
        const int cy = cell_coord(ay);

        // rings 0,1 + ovf already folded into fast's best
        unsigned long long best = (lane == 0) ? g_fail_best[f]
                                              : 0xFFFFFFFFFFFFFFFFull;
        best = __shfl_sync(0xffffffffu, best, 0);

        for (int r = 2; ; ++r) {
            int nc = 8 * r;
            for (int tc = lane; tc < nc; tc += 32) {
                int i, j;
                if (tc < 2 * r + 1)      { i = cx - r + tc;               j = cy - r; }
                else if (tc < 4 * r + 2) { i = cx - r + (tc - (2*r + 1)); j = cy + r; }
                else { int s = tc - (4*r + 2); j = cy - r + 1 + (s >> 1);
                       i = (s & 1) ? cx + r : cx - r; }
                if ((unsigned)i < G && (unsigned)j < G)
                    scan_hcell((j + 1) * GH + (i + 1), ax, ay, best);
            }
            #pragma unroll
            for (int m = 16; m >= 1; m >>= 1)
                best = min(best, __shfl_xor_sync(0xffffffffu, best, m));

            if (cx - r <= 0 && cx + r >= G - 1 &&
                cy - r <= 0 && cy + r >= G - 1) break;
            float mb = __int_as_float(0x7f800000);
            if (cx - r > 0)     mb = fminf(mb, ax - (X0 + (float)(cx - r) * H));
            if (cx + r < G - 1) mb = fminf(mb, (X0 + (float)(cx + r + 1) * H) - ax);
            if (cy - r > 0)     mb = fminf(mb, ay - (X0 + (float)(cy - r) * H));
            if (cy + r < G - 1) mb = fminf(mb, (X0 + (float)(cy + r + 1) * H) - ay);
            float bd = __uint_as_float((unsigned)(best >> 32));
            if (bd <= mb - EPS) break;
        }

        if (lane == 0)
            ((float2*)out)[q] = fetch_win(best, ax, ay);
    }
}

extern "C" void kernel_launch(void* const* d_in, const int* in_sizes, int n_in,
                              void* d_out, int out_size)
{
    const float* A = (const float*)d_in[0];   // [Q, 2]
    const float* B = (const float*)d_in[1];   // [2, N]
    float*     out = (float*)d_out;           // [Q, 2]

    const int Q = in_sizes[0] / 2;
    const int N = in_sizes[1] / 2;

    zero_k  <<<(NH + 255) / 256, 256>>>();
    bucket_k<<<(N + 255) / 256, 256>>>(B, N);

    fast_k<<<(Q * 4 + 255) / 256, 256>>>(A, out, Q);

    const int slow_blocks = 128;              // 1024 warps, grid-stride
    slow_k<<<slow_blocks, 256>>>(A, out, slow_blocks * 8);
}